// round 14
// baseline (speedup 1.0000x reference)
#include <cuda_runtime.h>
#include <cuda_bf16.h>
#include <stdint.h>

#define NN     65536      // nodes = 256*256
#define NEDGE  524288     // 8*NN
#define CCH    64

// ---------------- device scratch (static, no allocation) ----------------
__device__ float g_xn [NN*CCH];
__device__ float g_xl0[NN*CCH];
__device__ float g_xr0[NN*CCH];
__device__ float g_xl1[NN*CCH];
__device__ float g_xr1[NN*CCH];
__device__ float g_xl2[NN*CCH];
__device__ float g_xr2[NN*CCH];
// packed bf16 hi/lo activation planes: [node][32 kwords]
__device__ uint32_t g_xnh[NN*32], g_xnl[NN*32];
__device__ uint32_t g_tph[3][NN*32], g_tpl[3][NN*32];   // per-branch layer tmp
__device__ uint32_t g_bph[3][NN*32], g_bpl[3][NN*32];   // per-branch output
// pre-converted weights
__device__ uint32_t g_gwh[27*128*32], g_gwl[27*128*32]; // gat W planes [wi][n(128)][kp]
__device__ uint32_t g_cwh[3*64*96],  g_cwl[3*64*96];    // combine W [st][o][96]
__device__ uint32_t g_wbh[16*4*64*72];                  // conv W hi
__device__ uint32_t g_wbl[16*4*64*72];                  // conv W lo
__device__ int   g_rp [NN+1];
__device__ int   g_cnt[NN];
__device__ int   g_csrc[NEDGE];

// ---------------- static streams/events for fork-join (created pre-main) ----
struct HxAsync {
    cudaStream_t s1, s2;
    cudaEvent_t  ef, e1, e2;
    bool ok;
    HxAsync(){
        ok = true;
        ok &= (cudaStreamCreateWithFlags(&s1, cudaStreamNonBlocking) == cudaSuccess);
        ok &= (cudaStreamCreateWithFlags(&s2, cudaStreamNonBlocking) == cudaSuccess);
        ok &= (cudaEventCreateWithFlags(&ef, cudaEventDisableTiming) == cudaSuccess);
        ok &= (cudaEventCreateWithFlags(&e1, cudaEventDisableTiming) == cudaSuccess);
        ok &= (cudaEventCreateWithFlags(&e2, cudaEventDisableTiming) == cudaSuccess);
    }
};
static HxAsync g_hx;

// ---------------- bf16 split / mma / ldsm helpers ----------------
__device__ __forceinline__ void hl2(float x, float y, uint32_t& hw, uint32_t& lw){
    __nv_bfloat16 hx = __float2bfloat16(x);
    __nv_bfloat16 hy = __float2bfloat16(y);
    __nv_bfloat16 lx = __float2bfloat16(x - __bfloat162float(hx));
    __nv_bfloat16 ly = __float2bfloat16(y - __bfloat162float(hy));
    hw = ((uint32_t)__bfloat16_as_ushort(hy) << 16) | (uint32_t)__bfloat16_as_ushort(hx);
    lw = ((uint32_t)__bfloat16_as_ushort(ly) << 16) | (uint32_t)__bfloat16_as_ushort(lx);
}
__device__ __forceinline__ void mma16(float d[4], const uint32_t a[4], const uint32_t b[2]){
    asm volatile("mma.sync.aligned.m16n8k16.row.col.f32.bf16.bf16.f32 "
                 "{%0,%1,%2,%3},{%4,%5,%6,%7},{%8,%9},{%0,%1,%2,%3};"
                 : "+f"(d[0]), "+f"(d[1]), "+f"(d[2]), "+f"(d[3])
                 : "r"(a[0]), "r"(a[1]), "r"(a[2]), "r"(a[3]),
                   "r"(b[0]), "r"(b[1]));
}
__device__ __forceinline__ uint32_t sptr(const void* p){
    uint32_t s;
    asm("{ .reg .u64 t; cvta.to.shared.u64 t, %1; cvt.u32.u64 %0, t; }"
        : "=r"(s) : "l"(p));
    return s;
}
__device__ __forceinline__ void ldsm4(uint32_t d[4], uint32_t a){
    asm volatile("ldmatrix.sync.aligned.m8n8.x4.shared.b16 {%0,%1,%2,%3}, [%4];"
                 : "=r"(d[0]), "=r"(d[1]), "=r"(d[2]), "=r"(d[3]) : "r"(a));
}

// ---------------- small utility kernels ----------------
__global__ void zero_int_k(int* p, int n){
    int i = blockIdx.x*blockDim.x + threadIdx.x;
    if (i < n) p[i] = 0;
}

__global__ void hist_k(const int* __restrict__ dst, int* __restrict__ cnt){
    int i = blockIdx.x*blockDim.x + threadIdx.x;
    if (i < NEDGE) atomicAdd(&cnt[dst[i]], 1);
}

__global__ void scan_k(const int* __restrict__ cnt, int* __restrict__ rp){
    __shared__ int s[1024];
    int t = threadIdx.x;
    int base = t * 64;
    int sum = 0;
    #pragma unroll 4
    for (int i = 0; i < 64; i++) sum += cnt[base+i];
    s[t] = sum;
    __syncthreads();
    for (int off = 1; off < 1024; off <<= 1){
        int v = (t >= off) ? s[t-off] : 0;
        __syncthreads();
        s[t] += v;
        __syncthreads();
    }
    int run = (t == 0) ? 0 : s[t-1];
    for (int i = 0; i < 64; i++){ rp[base+i] = run; run += cnt[base+i]; }
    if (t == 1023) rp[NN] = run;
}

// self-cleaning: consumes cnt back down to zero
__global__ void fill_k(const int* __restrict__ src, const int* __restrict__ dst,
                       const int* __restrict__ rp, int* __restrict__ cur,
                       int* __restrict__ csrc){
    int i = blockIdx.x*blockDim.x + threadIdx.x;
    if (i < NEDGE){
        int d = dst[i];
        int p = rp[d] + atomicSub(&cur[d], 1) - 1;
        csrc[p] = src[i];
    }
}

// gat weights -> planes [wi][n(128)][kp(32)]
__global__ void wtrans_gat_k(const float* __restrict__ Wl, const float* __restrict__ Wr,
                             uint32_t* __restrict__ ph, uint32_t* __restrict__ pl){
    int i = blockIdx.x*blockDim.x + threadIdx.x;
    if (i >= 27*128*32) return;
    int kp = i & 31;
    int n  = (i >> 5) & 127;
    int wi = i >> 12;
    float w0, w1;
    if (n < 64){
        w0 = Wl[(size_t)wi*4096 + (2*kp)*64 + n];
        w1 = Wl[(size_t)wi*4096 + (2*kp+1)*64 + n];
    } else {
        w0 = Wr[(size_t)wi*4096 + (2*kp)*64 + n-64];
        w1 = Wr[(size_t)wi*4096 + (2*kp+1)*64 + n-64];
    }
    uint32_t hw, lw; hl2(w0, w1, hw, lw);
    ph[i] = hw; pl[i] = lw;
}

// combine weights -> [st][o(64)][w(96)]
__global__ void wtrans_cc_k(const float* __restrict__ W,
                            uint32_t* __restrict__ ph, uint32_t* __restrict__ pl){
    int i = blockIdx.x*blockDim.x + threadIdx.x;
    if (i >= 3*64*96) return;
    int w  = i % 96;
    int o  = (i / 96) & 63;
    int st = i / (96*64);
    int cg = w >> 5, kp = w & 31;
    float w0 = W[(size_t)st*12288 + o*192 + cg*64 + 2*kp];
    float w1 = W[(size_t)st*12288 + o*192 + cg*64 + 2*kp + 1];
    uint32_t hw, lw; hl2(w0, w1, hw, lw);
    ph[i] = hw; pl[i] = lw;
}

// conv weights
__global__ void wtrans_bf16_k(const float* __restrict__ rw,
                              uint32_t* __restrict__ wbh, uint32_t* __restrict__ wbl){
    int i = blockIdx.x*blockDim.x + threadIdx.x;
    if (i >= 16*4*64*72) return;
    int w    = i % 72;
    int oc   = (i / 72) & 63;
    int chunk= (i / (72*64)) & 3;
    int conv = i / (72*64*4);
    int t    = w >> 3;
    int cp   = w & 7;
    int ci0  = chunk*16 + 2*cp;
    float x0 = rw[ ((size_t)(conv*64 + oc)*64 + ci0    )*9 + t ];
    float x1 = rw[ ((size_t)(conv*64 + oc)*64 + ci0 + 1)*9 + t ];
    uint32_t hw, lw; hl2(x0, x1, hw, lw);
    wbh[i] = hw; wbl[i] = lw;
}

// fp32 node-major -> packed hi/lo planes
__global__ void cvt_planes_k(const float* __restrict__ x,
                             uint32_t* __restrict__ ph, uint32_t* __restrict__ pl){
    int i = blockIdx.x*blockDim.x + threadIdx.x;
    if (i >= NN*32) return;
    float2 v = ((const float2*)x)[i];
    uint32_t hw, lw; hl2(v.x, v.y, hw, lw);
    ph[i] = hw; pl[i] = lw;
}

// out[col][row] = in[row][col]
__global__ void transpose_k(const float* __restrict__ in, float* __restrict__ out,
                            int rows, int cols){
    __shared__ float tile[32][33];
    int bx = blockIdx.x << 5;
    int by = blockIdx.y << 5;
    int tx = threadIdx.x, ty = threadIdx.y;
    #pragma unroll
    for (int j = 0; j < 32; j += 8)
        tile[ty+j][tx] = in[(size_t)(by+ty+j)*cols + bx + tx];
    __syncthreads();
    #pragma unroll
    for (int j = 0; j < 32; j += 8)
        out[(size_t)(bx+ty+j)*rows + by + tx] = tile[tx][ty+j];
}

// ---------------- dual GEMM via ldmatrix + 3x bf16 mma ----------------
// block 256 thr / 8 warps; tile M=64 x N=128; K=64; 1024 blocks; 4 blocks/SM
__global__ __launch_bounds__(256, 4)
void gemm_dual_mma_k(const uint32_t* __restrict__ ah,
                     const uint32_t* __restrict__ al,
                     const uint32_t* __restrict__ bh,
                     const uint32_t* __restrict__ bl,
                     float* __restrict__ ol, float* __restrict__ orr){
    extern __shared__ uint32_t sm[];
    uint32_t* amh = sm;            // 64*36 = 2304
    uint32_t* aml = amh + 2304;
    uint32_t* bmh = aml + 2304;    // 128*36 = 4608
    uint32_t* bml = bmh + 4608;
    int tid = threadIdx.x, lane = tid & 31, wid = tid >> 5;
    int q = lane >> 2, r = lane & 3;
    size_t rbase = (size_t)blockIdx.x * 64;
    int wm  = (wid & 1) << 5;
    int wnn = (wid >> 1) << 5;

    const uint4* a4h = (const uint4*)(ah + rbase*32);
    const uint4* a4l = (const uint4*)(al + rbase*32);
    for (int i = tid; i < 512; i += 256){
        int row = i >> 3, c4 = (i & 7) << 2;
        *(uint4*)&amh[row*36 + c4] = a4h[i];
        *(uint4*)&aml[row*36 + c4] = a4l[i];
    }
    const uint4* b4h = (const uint4*)bh;
    const uint4* b4l = (const uint4*)bl;
    for (int i = tid; i < 1024; i += 256){
        int n = i >> 3, c4 = (i & 7) << 2;
        *(uint4*)&bmh[n*36 + c4] = b4h[i];
        *(uint4*)&bml[n*36 + c4] = b4l[i];
    }
    __syncthreads();

    int arow0 = wm + (lane & 7) + ((lane >> 3) & 1)*8;
    uint32_t aoff = (uint32_t)(arow0*36 + ((lane >> 4) & 1)*4) * 4;
    uint32_t AH = sptr(amh) + aoff, AL = sptr(aml) + aoff;
    int brow0 = wnn + ((lane >> 4) & 1)*8 + (lane & 7);
    uint32_t boff = (uint32_t)(brow0*36 + ((lane >> 3) & 1)*4) * 4;
    uint32_t BH = sptr(bmh) + boff, BL = sptr(bml) + boff;

    float acc[2][4][4];
    #pragma unroll
    for (int a=0;a<2;a++)
        #pragma unroll
        for (int b=0;b<4;b++)
            #pragma unroll
            for (int c=0;c<4;c++) acc[a][b][c] = 0.f;

    #pragma unroll
    for (int kk = 0; kk < 4; kk++){
        uint32_t Ah[2][4], Al[2][4];
        ldsm4(Ah[0], AH + kk*32);
        ldsm4(Ah[1], AH + 16*36*4 + kk*32);
        ldsm4(Al[0], AL + kk*32);
        ldsm4(Al[1], AL + 16*36*4 + kk*32);
        #pragma unroll
        for (int ntp = 0; ntp < 2; ntp++){
            uint32_t Bh4[4], Bl4[4];
            ldsm4(Bh4, BH + ntp*16*36*4 + kk*32);
            ldsm4(Bl4, BL + ntp*16*36*4 + kk*32);
            #pragma unroll
            for (int mt = 0; mt < 2; mt++){
                mma16(acc[mt][2*ntp],   Ah[mt], &Bh4[0]);
                mma16(acc[mt][2*ntp],   Ah[mt], &Bl4[0]);
                mma16(acc[mt][2*ntp],   Al[mt], &Bh4[0]);
                mma16(acc[mt][2*ntp+1], Ah[mt], &Bh4[2]);
                mma16(acc[mt][2*ntp+1], Ah[mt], &Bl4[2]);
                mma16(acc[mt][2*ntp+1], Al[mt], &Bh4[2]);
            }
        }
    }

    bool left = (wnn < 64);
    float* op = left ? ol : orr;
    int n0 = left ? wnn : (wnn - 64);
    #pragma unroll
    for (int mt = 0; mt < 2; mt++)
        #pragma unroll
        for (int rr = 0; rr < 2; rr++){
            size_t row = rbase + wm + mt*16 + rr*8 + q;
            #pragma unroll
            for (int nt = 0; nt < 4; nt++){
                int oc = n0 + (nt<<3) + (r<<1);
                float2 v = make_float2(acc[mt][nt][rr*2], acc[mt][nt][rr*2+1]);
                *(float2*)(op + row*64 + oc) = v;
            }
        }
}

// ---------------- GATv2 edge aggregation (unchanged) ----------------
__global__ void gat_agg_k(const float* __restrict__ xl, const float* __restrict__ xr,
                          const int* __restrict__ rp, const int* __restrict__ cs,
                          const float* __restrict__ att, const float* __restrict__ bias,
                          uint32_t* __restrict__ oh, uint32_t* __restrict__ olp){
    int gw   = (blockIdx.x*blockDim.x + threadIdx.x) >> 5;
    int lane = threadIdx.x & 31;
    if (gw >= NN) return;
    float2 xi = __ldg(&((const float2*)xr)[gw*32 + lane]);
    float2 av = __ldg(&((const float2*)att)[lane]);
    float den = 0.f, ac0 = 0.f, ac1 = 0.f;
    int k0 = __ldg(&rp[gw]), k1 = __ldg(&rp[gw+1]);
    #pragma unroll 4
    for (int k = k0; k < k1; k++){
        int s = __ldg(&cs[k]);
        float2 xj = __ldg(&((const float2*)xl)[s*32 + lane]);
        float t0 = xi.x + xj.x; t0 = fmaxf(t0, 0.2f*t0);
        float t1 = xi.y + xj.y; t1 = fmaxf(t1, 0.2f*t1);
        float p = av.x*t0 + av.y*t1;
        p += __shfl_xor_sync(0xffffffffu, p, 1);
        p += __shfl_xor_sync(0xffffffffu, p, 2);
        p += __shfl_xor_sync(0xffffffffu, p, 4);
        float w = __expf(p);
        den += w;
        ac0 += w*xj.x;
        ac1 += w*xj.y;
    }
    float2 bv = __ldg(&((const float2*)bias)[lane]);
    float inv = 1.f/(den + 1e-16f);
    float o0 = ac0*inv + bv.x;
    float o1 = ac1*inv + bv.y;
    o0 = (o0 > 0.f) ? o0 : (__expf(o0) - 1.f);   // ELU
    o1 = (o1 > 0.f) ? o1 : (__expf(o1) - 1.f);
    uint32_t hw, lw; hl2(o0, o1, hw, lw);
    oh [gw*32 + lane] = hw;
    olp[gw*32 + lane] = lw;
}

// ---------------- combine via ldmatrix (unchanged) ----------------
__global__ void combine_mma_k(const uint32_t* __restrict__ b0h, const uint32_t* __restrict__ b0l,
                              const uint32_t* __restrict__ b1h, const uint32_t* __restrict__ b1l,
                              const uint32_t* __restrict__ b2h, const uint32_t* __restrict__ b2l,
                              const uint32_t* __restrict__ cwh, const uint32_t* __restrict__ cwl,
                              const float* __restrict__ bias,
                              float* __restrict__ xio,
                              uint32_t* __restrict__ oph, uint32_t* __restrict__ opl){
    extern __shared__ uint32_t sm[];
    uint32_t* amh = sm;            // 128*36 = 4608
    uint32_t* aml = amh + 4608;
    uint32_t* bmh = aml + 4608;    // 64*36 = 2304
    uint32_t* bml = bmh + 2304;
    int tid = threadIdx.x, lane = tid & 31, wid = tid >> 5;
    int q = lane >> 2, r = lane & 3;
    size_t rbase = (size_t)blockIdx.x * 128;
    int wm = (wid & 3) << 5;
    int wn = (wid >> 2) << 5;

    int arow0 = wm + (lane & 7) + ((lane >> 3) & 1)*8;
    uint32_t aoff = (uint32_t)(arow0*36 + ((lane >> 4) & 1)*4) * 4;
    uint32_t AH = sptr(amh) + aoff, AL = sptr(aml) + aoff;
    int brow0 = wn + ((lane >> 4) & 1)*8 + (lane & 7);
    uint32_t boff = (uint32_t)(brow0*36 + ((lane >> 3) & 1)*4) * 4;
    uint32_t BH = sptr(bmh) + boff, BL = sptr(bml) + boff;

    float acc[2][4][4];
    #pragma unroll
    for (int a=0;a<2;a++)
        #pragma unroll
        for (int b=0;b<4;b++)
            #pragma unroll
            for (int c=0;c<4;c++) acc[a][b][c] = 0.f;

    const uint4* w4h = (const uint4*)cwh;
    const uint4* w4l = (const uint4*)cwl;

    #pragma unroll 1
    for (int cg = 0; cg < 3; cg++){
        const uint32_t* bsh = (cg==0) ? b0h : (cg==1) ? b1h : b2h;
        const uint32_t* bsl = (cg==0) ? b0l : (cg==1) ? b1l : b2l;
        const uint4* s4h = (const uint4*)(bsh + rbase*32);
        const uint4* s4l = (const uint4*)(bsl + rbase*32);
        for (int i = tid; i < 1024; i += 256){
            int row = i >> 3, c4 = (i & 7) << 2;
            *(uint4*)&amh[row*36 + c4] = s4h[i];
            *(uint4*)&aml[row*36 + c4] = s4l[i];
        }
        for (int i = tid; i < 512; i += 256){
            int o = i >> 3, c = i & 7;
            *(uint4*)&bmh[o*36 + (c<<2)] = w4h[o*24 + cg*8 + c];
            *(uint4*)&bml[o*36 + (c<<2)] = w4l[o*24 + cg*8 + c];
        }
        __syncthreads();

        #pragma unroll
        for (int kk = 0; kk < 4; kk++){
            uint32_t Ah[2][4], Al[2][4];
            ldsm4(Ah[0], AH + kk*32);
            ldsm4(Ah[1], AH + 16*36*4 + kk*32);
            ldsm4(Al[0], AL + kk*32);
            ldsm4(Al[1], AL + 16*36*4 + kk*32);
            #pragma unroll
            for (int ntp = 0; ntp < 2; ntp++){
                uint32_t Bh4[4], Bl4[4];
                ldsm4(Bh4, BH + ntp*16*36*4 + kk*32);
                ldsm4(Bl4, BL + ntp*16*36*4 + kk*32);
                #pragma unroll
                for (int mt = 0; mt < 2; mt++){
                    mma16(acc[mt][2*ntp],   Ah[mt], &Bh4[0]);
                    mma16(acc[mt][2*ntp],   Ah[mt], &Bl4[0]);
                    mma16(acc[mt][2*ntp],   Al[mt], &Bh4[0]);
                    mma16(acc[mt][2*ntp+1], Ah[mt], &Bh4[2]);
                    mma16(acc[mt][2*ntp+1], Ah[mt], &Bl4[2]);
                    mma16(acc[mt][2*ntp+1], Al[mt], &Bh4[2]);
                }
            }
        }
        __syncthreads();
    }

    #pragma unroll
    for (int mt = 0; mt < 2; mt++)
        #pragma unroll
        for (int rr = 0; rr < 2; rr++){
            size_t row = rbase + wm + mt*16 + rr*8 + q;
            #pragma unroll
            for (int nt = 0; nt < 4; nt++){
                int oc = wn + (nt<<3) + (r<<1);
                float2 res = *(float2*)(xio + row*64 + oc);
                float v0 = acc[mt][nt][rr*2]   + bias[oc]   + res.x;
                float v1 = acc[mt][nt][rr*2+1] + bias[oc+1] + res.y;
                *(float2*)(xio + row*64 + oc) = make_float2(v0, v1);
                uint32_t hw, lw; hl2(v0, v1, hw, lw);
                oph[row*32 + (oc>>1)] = hw;
                opl[row*32 + (oc>>1)] = lw;
            }
        }
}

// ---------------- 3x3 conv: 512 blocks x 128 px, 8 warps, plane input ---------
// A smem interleaved: per pixel 20 words = 8 hi + 8 lo + 4 pad (stride 20 mod 32
// gives conflict-free 8-row LDSM banks). Halo row = 130 cols. 68.5 KB smem ->
// 3 blocks/SM (launch_bounds enforces reg budget).
// mode 0: planes(PReLU(conv+bias)) only;  mode 1: fp32 out += conv+bias, + planes
__global__ __launch_bounds__(256, 3)
void conv3_mma_k(const uint32_t* __restrict__ inh,
                 const uint32_t* __restrict__ inl,
                 const uint32_t* __restrict__ wbh,
                 const uint32_t* __restrict__ wbl,
                 const float* __restrict__ bias,
                 const float* __restrict__ aptr,
                 float* __restrict__ out, int mode,
                 uint32_t* __restrict__ ph, uint32_t* __restrict__ pl){
    extern __shared__ uint32_t sm[];
    uint32_t* am  = sm;            // 3*130*20 = 7800 (hi @ +0..7, lo @ +8..15)
    uint32_t* bmh = am + 7800;     // 64*76 = 4864
    uint32_t* bml = bmh + 4864;
    int tid = threadIdx.x, lane = tid & 31, wid = tid >> 5;
    int q = lane >> 2, r = lane & 3;
    int h  = blockIdx.x >> 1;
    int w0 = (blockIdx.x & 1) << 7;
    int wpx = (wid & 3) << 5;
    int wn  = (wid >> 2) << 5;

    int pxo  = (lane & 7) + ((lane >> 3) & 1)*8;
    uint32_t akp = ((lane >> 4) & 1)*4;
    uint32_t AHb = sptr(am) + akp*4;
    uint32_t ALb = AHb + 32;                     // +8 words: lo block
    int brow0 = wn + ((lane >> 4) & 1)*8 + (lane & 7);
    uint32_t boff = (uint32_t)(brow0*76 + ((lane >> 3) & 1)*4) * 4;
    uint32_t BH = sptr(bmh) + boff, BL = sptr(bml) + boff;

    float acc[2][4][4];
    #pragma unroll
    for (int a=0;a<2;a++)
        #pragma unroll
        for (int b=0;b<4;b++)
            #pragma unroll
            for (int c=0;c<4;c++) acc[a][b][c] = 0.f;

    for (int chunk = 0; chunk < 4; chunk++){
        const uint4* wh4 = (const uint4*)(wbh + chunk*4608);
        const uint4* wl4 = (const uint4*)(wbl + chunk*4608);
        for (int i = tid; i < 1152; i += 256){
            int oc = i / 18, w4 = i - oc*18;
            *(uint4*)&bmh[oc*76 + (w4<<2)] = wh4[i];
            *(uint4*)&bml[oc*76 + (w4<<2)] = wl4[i];
        }
        // A tile: pure uint4 copy from packed planes into interleaved layout
        for (int i = tid; i < 1560; i += 256){
            int pos = i >> 2, sel = i & 3;
            int kh = pos / 130, col = pos - kh*130;
            int gh = h - 1 + kh, gw = w0 - 1 + col;
            uint4 v = make_uint4(0u,0u,0u,0u);
            const uint32_t* srcp = (sel >> 1) ? inl : inh;
            if ((unsigned)gh < 256u && (unsigned)gw < 256u)
                v = *(const uint4*)(srcp + ((size_t)((gh<<8)+gw))*32 + (chunk<<3) + ((sel&1)<<2));
            *(uint4*)&am[(kh*130 + col)*20 + ((sel>>1)<<3) + ((sel&1)<<2)] = v;
        }
        __syncthreads();

        #pragma unroll
        for (int t = 0; t < 9; t++){
            int kh = t/3, kw = t - (t/3)*3;
            uint32_t Ah[2][4], Al[2][4];
            #pragma unroll
            for (int mt = 0; mt < 2; mt++){
                uint32_t ao = (uint32_t)((kh*130 + wpx + kw + pxo + mt*16)*20) * 4;
                ldsm4(Ah[mt], AHb + ao);
                ldsm4(Al[mt], ALb + ao);
            }
            #pragma unroll
            for (int ntp = 0; ntp < 2; ntp++){
                uint32_t Bh4[4], Bl4[4];
                ldsm4(Bh4, BH + (uint32_t)(ntp*16*76 + t*8)*4);
                ldsm4(Bl4, BL + (uint32_t)(ntp*16*76 + t*8)*4);
                #pragma unroll
                for (int mt = 0; mt < 2; mt++){
                    mma16(acc[mt][2*ntp],   Ah[mt], &Bh4[0]);
                    mma16(acc[mt][2*ntp],   Ah[mt], &Bl4[0]);
                    mma16(acc[mt][2*ntp],   Al[mt], &Bh4[0]);
                    mma16(acc[mt][2*ntp+1], Ah[mt], &Bh4[2]);
                    mma16(acc[mt][2*ntp+1], Ah[mt], &Bl4[2]);
                    mma16(acc[mt][2*ntp+1], Al[mt], &Bh4[2]);
                }
            }
        }
        __syncthreads();
    }

    float a = aptr[0];
    #pragma unroll
    for (int mt = 0; mt < 2; mt++)
        #pragma unroll
        for (int rr = 0; rr < 2; rr++){
            int px = wpx + mt*16 + rr*8 + q;
            size_t node = ((size_t)h << 8) + w0 + px;
            #pragma unroll
            for (int nt = 0; nt < 4; nt++){
                int oc = wn + (nt<<3) + (r<<1);
                float v0 = acc[mt][nt][rr*2]   + bias[oc];
                float v1 = acc[mt][nt][rr*2+1] + bias[oc+1];
                if (mode == 0){
                    v0 = (v0 >= 0.f) ? v0 : a*v0;
                    v1 = (v1 >= 0.f) ? v1 : a*v1;
                } else {
                    float* op = out + node*64 + oc;
                    float2 cur = *(float2*)op;
                    v0 += cur.x; v1 += cur.y;
                    *(float2*)op = make_float2(v0, v1);
                }
                uint32_t hw, lw; hl2(v0, v1, hw, lw);
                ph[node*32 + (oc>>1)] = hw;
                pl[node*32 + (oc>>1)] = lw;
            }
        }
}

// ---------------- host orchestration ----------------
extern "C" void kernel_launch(void* const* d_in, const int* in_sizes, int n_in,
                              void* d_out, int out_size){
    const float* x    = (const float*)d_in[0];
    const int*   ei   = (const int*)  d_in[1];
    const float* gWl  = (const float*)d_in[2];
    const float* gWr  = (const float*)d_in[3];
    const float* gatt = (const float*)d_in[4];
    const float* gb   = (const float*)d_in[5];
    const float* ccw  = (const float*)d_in[6];
    const float* ccb  = (const float*)d_in[7];
    const float* rbw  = (const float*)d_in[8];
    const float* rbb  = (const float*)d_in[9];
    const float* rba  = (const float*)d_in[10];
    float* outp = (float*)d_out;

    float *xn,*xl0,*xr0,*xl1,*xr1,*xl2,*xr2;
    uint32_t *xnh,*xnl,*tph,*tpl,*bph,*bpl,*gwh,*gwl,*cwh,*cwl,*wbh,*wbl;
    int *rp,*cnt,*csrc;
    cudaGetSymbolAddress((void**)&xn,  g_xn);
    cudaGetSymbolAddress((void**)&xl0, g_xl0);
    cudaGetSymbolAddress((void**)&xr0, g_xr0);
    cudaGetSymbolAddress((void**)&xl1, g_xl1);
    cudaGetSymbolAddress((void**)&xr1, g_xr1);
    cudaGetSymbolAddress((void**)&xl2, g_xl2);
    cudaGetSymbolAddress((void**)&xr2, g_xr2);
    cudaGetSymbolAddress((void**)&xnh, g_xnh);
    cudaGetSymbolAddress((void**)&xnl, g_xnl);
    cudaGetSymbolAddress((void**)&tph, g_tph);
    cudaGetSymbolAddress((void**)&tpl, g_tpl);
    cudaGetSymbolAddress((void**)&bph, g_bph);
    cudaGetSymbolAddress((void**)&bpl, g_bpl);
    cudaGetSymbolAddress((void**)&gwh, g_gwh);
    cudaGetSymbolAddress((void**)&gwl, g_gwl);
    cudaGetSymbolAddress((void**)&cwh, g_cwh);
    cudaGetSymbolAddress((void**)&cwl, g_cwl);
    cudaGetSymbolAddress((void**)&wbh, g_wbh);
    cudaGetSymbolAddress((void**)&wbl, g_wbl);
    cudaGetSymbolAddress((void**)&rp,  g_rp);
    cudaGetSymbolAddress((void**)&cnt, g_cnt);
    cudaGetSymbolAddress((void**)&csrc,g_csrc);

    const int smem_gemm = 13824*4;   // 55296 B
    const int smem_comb = 13824*4;   // 55296 B
    const int smem_conv = 17528*4;   // 70112 B
    cudaFuncSetAttribute(gemm_dual_mma_k, cudaFuncAttributeMaxDynamicSharedMemorySize, smem_gemm);
    cudaFuncSetAttribute(combine_mma_k,   cudaFuncAttributeMaxDynamicSharedMemorySize, smem_comb);
    cudaFuncSetAttribute(conv3_mma_k,     cudaFuncAttributeMaxDynamicSharedMemorySize, smem_conv);

    bool async_ok = g_hx.ok;
    cudaStream_t st1 = async_ok ? g_hx.s1 : (cudaStream_t)0;
    cudaStream_t st2 = async_ok ? g_hx.s2 : (cudaStream_t)0;

    // launches 1-4 (4th = profiled gemm)
    wtrans_gat_k<<<(27*128*32)/256, 256>>>(gWl, gWr, gwh, gwl);          // 1
    transpose_k<<<dim3(2048,2), dim3(32,8)>>>(x, xn, 64, 65536);         // 2
    cvt_planes_k<<<(NN*32)/256, 256>>>(xn, xnh, xnl);                    // 3
    gemm_dual_mma_k<<<1024, 256, smem_gemm>>>(xnh, xnl, gwh, gwl, xl0, xr0); // 4
    zero_int_k<<<NN/256, 256>>>(cnt, NN);                                // 5
    hist_k<<<NEDGE/256, 256>>>(ei + NEDGE, cnt);                         // 6
    scan_k<<<1, 1024>>>(cnt, rp);                                        // 7
    fill_k<<<NEDGE/256, 256>>>(ei, ei + NEDGE, rp, cnt, csrc);           // 8
    wtrans_bf16_k<<<(16*4*64*72)/256, 256>>>(rbw, wbh, wbl);             // 9
    wtrans_cc_k<<<(3*64*96)/256, 256>>>(ccw, cwh, cwl);                  // 10

    float* xlv[3] = {xl0, xl1, xl2};
    float* xrv[3] = {xr0, xr1, xr2};

    for (int st = 0; st < 3; st++){
        if (async_ok){
            cudaEventRecord(g_hx.ef, 0);
            cudaStreamWaitEvent(st1, g_hx.ef, 0);
            cudaStreamWaitEvent(st2, g_hx.ef, 0);
        }
        for (int mb = 0; mb < 3; mb++){
            cudaStream_t ss = (mb==0) ? (cudaStream_t)0 : (mb==1 ? st1 : st2);
            float* cxl = xlv[mb];
            float* cxr = xrv[mb];
            const uint32_t* curh = xnh;
            const uint32_t* curl = xnl;
            for (int l = 0; l < 3; l++){
                int wi = (st*3 + mb)*3 + l;
                uint32_t* dh = (l==0) ? (tph + (size_t)mb*NN*32) : (bph + (size_t)mb*NN*32);
                uint32_t* dl = (l==0) ? (tpl + (size_t)mb*NN*32) : (bpl + (size_t)mb*NN*32);
                if (!(st==0 && mb==0 && l==0))   // that gemm was pre-launched
                    gemm_dual_mma_k<<<1024, 256, smem_gemm, ss>>>(curh, curl,
                        gwh + (size_t)wi*4096, gwl + (size_t)wi*4096, cxl, cxr);
                gat_agg_k<<<(NN*32)/256, 256, 0, ss>>>(cxl, cxr, rp, csrc,
                        gatt + (size_t)wi*64, gb + (size_t)wi*64, dh, dl);
                curh = dh; curl = dl;
            }
        }
        if (async_ok){
            cudaEventRecord(g_hx.e1, st1);
            cudaEventRecord(g_hx.e2, st2);
            cudaStreamWaitEvent((cudaStream_t)0, g_hx.e1, 0);
            cudaStreamWaitEvent((cudaStream_t)0, g_hx.e2, 0);
        }
        combine_mma_k<<<512, 256, smem_comb>>>(
            bph, bpl,
            bph + (size_t)NN*32, bpl + (size_t)NN*32,
            bph + (size_t)2*NN*32, bpl + (size_t)2*NN*32,
            cwh + (size_t)st*6144, cwl + (size_t)st*6144,
            ccb + (size_t)st*64, xn, xnh, xnl);
        if (st < 2){
            for (int bl = 0; bl < 4; bl++){
                int cidx = st*8 + bl*2;
                conv3_mma_k<<<512, 256, smem_conv>>>(xnh, xnl,
                                                     wbh + (size_t)cidx*18432,
                                                     wbl + (size_t)cidx*18432,
                                                     rbb + (size_t)cidx*64,
                                                     rba + st*4 + bl, xl0, 0,
                                                     tph, tpl);
                conv3_mma_k<<<512, 256, smem_conv>>>(tph, tpl,
                                                     wbh + (size_t)(cidx+1)*18432,
                                                     wbl + (size_t)(cidx+1)*18432,
                                                     rbb + (size_t)(cidx+1)*64,
                                                     rba + st*4 + bl, xn, 1,
                                                     xnh, xnl);
            }
        }
    }
    transpose_k<<<dim3(2,2048), dim3(32,8)>>>(xn, outp, 65536, 64);
}

// round 16
// speedup vs baseline: 1.0465x; 1.0465x over previous
#include <cuda_runtime.h>
#include <cuda_bf16.h>
#include <stdint.h>

#define NN     65536      // nodes = 256*256
#define NEDGE  524288     // 8*NN
#define CCH    64

// ---------------- device scratch (static, no allocation) ----------------
__device__ float g_xn [NN*CCH];
__device__ float g_xl0[NN*CCH];
__device__ float g_xr0[NN*CCH];
__device__ float g_xl1[NN*CCH];
__device__ float g_xr1[NN*CCH];
__device__ float g_xl2[NN*CCH];
__device__ float g_xr2[NN*CCH];
// packed bf16 hi/lo activation planes: [node][32 kwords]
__device__ uint32_t g_xnh[NN*32], g_xnl[NN*32];
__device__ uint32_t g_tph[3][NN*32], g_tpl[3][NN*32];   // per-branch layer tmp
__device__ uint32_t g_bph[3][NN*32], g_bpl[3][NN*32];   // per-branch output
// pre-converted weights
__device__ uint32_t g_gwh[27*128*32], g_gwl[27*128*32]; // gat W planes [wi][n(128)][kp]
__device__ uint32_t g_cwh[3*64*96],  g_cwl[3*64*96];    // combine W [st][o][96]
__device__ uint32_t g_wbh[16*4*64*72];                  // conv W hi
__device__ uint32_t g_wbl[16*4*64*72];                  // conv W lo
__device__ int   g_rp [NN+1];
__device__ int   g_cnt[NN];
__device__ int   g_csrc[NEDGE];

// ---------------- static streams/events for fork-join (created pre-main) ----
struct HxAsync {
    cudaStream_t s1, s2;
    cudaEvent_t  e0, ef, e1, e2;
    bool ok;
    HxAsync(){
        ok = true;
        ok &= (cudaStreamCreateWithFlags(&s1, cudaStreamNonBlocking) == cudaSuccess);
        ok &= (cudaStreamCreateWithFlags(&s2, cudaStreamNonBlocking) == cudaSuccess);
        ok &= (cudaEventCreateWithFlags(&e0, cudaEventDisableTiming) == cudaSuccess);
        ok &= (cudaEventCreateWithFlags(&ef, cudaEventDisableTiming) == cudaSuccess);
        ok &= (cudaEventCreateWithFlags(&e1, cudaEventDisableTiming) == cudaSuccess);
        ok &= (cudaEventCreateWithFlags(&e2, cudaEventDisableTiming) == cudaSuccess);
    }
};
static HxAsync g_hx;

// ---------------- bf16 split / mma / ldsm helpers ----------------
__device__ __forceinline__ void hl2(float x, float y, uint32_t& hw, uint32_t& lw){
    __nv_bfloat16 hx = __float2bfloat16(x);
    __nv_bfloat16 hy = __float2bfloat16(y);
    __nv_bfloat16 lx = __float2bfloat16(x - __bfloat162float(hx));
    __nv_bfloat16 ly = __float2bfloat16(y - __bfloat162float(hy));
    hw = ((uint32_t)__bfloat16_as_ushort(hy) << 16) | (uint32_t)__bfloat16_as_ushort(hx);
    lw = ((uint32_t)__bfloat16_as_ushort(ly) << 16) | (uint32_t)__bfloat16_as_ushort(lx);
}
__device__ __forceinline__ void mma16(float d[4], const uint32_t a[4], const uint32_t b[2]){
    asm volatile("mma.sync.aligned.m16n8k16.row.col.f32.bf16.bf16.f32 "
                 "{%0,%1,%2,%3},{%4,%5,%6,%7},{%8,%9},{%0,%1,%2,%3};"
                 : "+f"(d[0]), "+f"(d[1]), "+f"(d[2]), "+f"(d[3])
                 : "r"(a[0]), "r"(a[1]), "r"(a[2]), "r"(a[3]),
                   "r"(b[0]), "r"(b[1]));
}
__device__ __forceinline__ uint32_t sptr(const void* p){
    uint32_t s;
    asm("{ .reg .u64 t; cvta.to.shared.u64 t, %1; cvt.u32.u64 %0, t; }"
        : "=r"(s) : "l"(p));
    return s;
}
__device__ __forceinline__ void ldsm4(uint32_t d[4], uint32_t a){
    asm volatile("ldmatrix.sync.aligned.m8n8.x4.shared.b16 {%0,%1,%2,%3}, [%4];"
                 : "=r"(d[0]), "=r"(d[1]), "=r"(d[2]), "=r"(d[3]) : "r"(a));
}

// ---------------- small utility kernels ----------------
__global__ void zero_int_k(int* p, int n){
    int i = blockIdx.x*blockDim.x + threadIdx.x;
    if (i < n) p[i] = 0;
}

__global__ void hist_k(const int* __restrict__ dst, int* __restrict__ cnt){
    int i = blockIdx.x*blockDim.x + threadIdx.x;
    if (i < NEDGE) atomicAdd(&cnt[dst[i]], 1);
}

__global__ void scan_k(const int* __restrict__ cnt, int* __restrict__ rp){
    __shared__ int s[1024];
    int t = threadIdx.x;
    int base = t * 64;
    int sum = 0;
    #pragma unroll 4
    for (int i = 0; i < 64; i++) sum += cnt[base+i];
    s[t] = sum;
    __syncthreads();
    for (int off = 1; off < 1024; off <<= 1){
        int v = (t >= off) ? s[t-off] : 0;
        __syncthreads();
        s[t] += v;
        __syncthreads();
    }
    int run = (t == 0) ? 0 : s[t-1];
    for (int i = 0; i < 64; i++){ rp[base+i] = run; run += cnt[base+i]; }
    if (t == 1023) rp[NN] = run;
}

// self-cleaning: consumes cnt back down to zero
__global__ void fill_k(const int* __restrict__ src, const int* __restrict__ dst,
                       const int* __restrict__ rp, int* __restrict__ cur,
                       int* __restrict__ csrc){
    int i = blockIdx.x*blockDim.x + threadIdx.x;
    if (i < NEDGE){
        int d = dst[i];
        int p = rp[d] + atomicSub(&cur[d], 1) - 1;
        csrc[p] = src[i];
    }
}

// gat weights -> planes [wi][n(128)][kp(32)]
__global__ void wtrans_gat_k(const float* __restrict__ Wl, const float* __restrict__ Wr,
                             uint32_t* __restrict__ ph, uint32_t* __restrict__ pl){
    int i = blockIdx.x*blockDim.x + threadIdx.x;
    if (i >= 27*128*32) return;
    int kp = i & 31;
    int n  = (i >> 5) & 127;
    int wi = i >> 12;
    float w0, w1;
    if (n < 64){
        w0 = Wl[(size_t)wi*4096 + (2*kp)*64 + n];
        w1 = Wl[(size_t)wi*4096 + (2*kp+1)*64 + n];
    } else {
        w0 = Wr[(size_t)wi*4096 + (2*kp)*64 + n-64];
        w1 = Wr[(size_t)wi*4096 + (2*kp+1)*64 + n-64];
    }
    uint32_t hw, lw; hl2(w0, w1, hw, lw);
    ph[i] = hw; pl[i] = lw;
}

// combine weights -> [st][o(64)][w(96)]
__global__ void wtrans_cc_k(const float* __restrict__ W,
                            uint32_t* __restrict__ ph, uint32_t* __restrict__ pl){
    int i = blockIdx.x*blockDim.x + threadIdx.x;
    if (i >= 3*64*96) return;
    int w  = i % 96;
    int o  = (i / 96) & 63;
    int st = i / (96*64);
    int cg = w >> 5, kp = w & 31;
    float w0 = W[(size_t)st*12288 + o*192 + cg*64 + 2*kp];
    float w1 = W[(size_t)st*12288 + o*192 + cg*64 + 2*kp + 1];
    uint32_t hw, lw; hl2(w0, w1, hw, lw);
    ph[i] = hw; pl[i] = lw;
}

// conv weights
__global__ void wtrans_bf16_k(const float* __restrict__ rw,
                              uint32_t* __restrict__ wbh, uint32_t* __restrict__ wbl){
    int i = blockIdx.x*blockDim.x + threadIdx.x;
    if (i >= 16*4*64*72) return;
    int w    = i % 72;
    int oc   = (i / 72) & 63;
    int chunk= (i / (72*64)) & 3;
    int conv = i / (72*64*4);
    int t    = w >> 3;
    int cp   = w & 7;
    int ci0  = chunk*16 + 2*cp;
    float x0 = rw[ ((size_t)(conv*64 + oc)*64 + ci0    )*9 + t ];
    float x1 = rw[ ((size_t)(conv*64 + oc)*64 + ci0 + 1)*9 + t ];
    uint32_t hw, lw; hl2(x0, x1, hw, lw);
    wbh[i] = hw; wbl[i] = lw;
}

// fp32 node-major -> packed hi/lo planes
__global__ void cvt_planes_k(const float* __restrict__ x,
                             uint32_t* __restrict__ ph, uint32_t* __restrict__ pl){
    int i = blockIdx.x*blockDim.x + threadIdx.x;
    if (i >= NN*32) return;
    float2 v = ((const float2*)x)[i];
    uint32_t hw, lw; hl2(v.x, v.y, hw, lw);
    ph[i] = hw; pl[i] = lw;
}

// out[col][row] = in[row][col]
__global__ void transpose_k(const float* __restrict__ in, float* __restrict__ out,
                            int rows, int cols){
    __shared__ float tile[32][33];
    int bx = blockIdx.x << 5;
    int by = blockIdx.y << 5;
    int tx = threadIdx.x, ty = threadIdx.y;
    #pragma unroll
    for (int j = 0; j < 32; j += 8)
        tile[ty+j][tx] = in[(size_t)(by+ty+j)*cols + bx + tx];
    __syncthreads();
    #pragma unroll
    for (int j = 0; j < 32; j += 8)
        out[(size_t)(bx+ty+j)*rows + by + tx] = tile[tx][ty+j];
}

// ---------------- dual GEMM via ldmatrix + 3x bf16 mma ----------------
// block 256 thr / 8 warps; tile M=64 x N=128; K=64; 1024 blocks; 4 blocks/SM
__global__ __launch_bounds__(256, 4)
void gemm_dual_mma_k(const uint32_t* __restrict__ ah,
                     const uint32_t* __restrict__ al,
                     const uint32_t* __restrict__ bh,
                     const uint32_t* __restrict__ bl,
                     float* __restrict__ ol, float* __restrict__ orr){
    extern __shared__ uint32_t sm[];
    uint32_t* amh = sm;            // 64*36 = 2304
    uint32_t* aml = amh + 2304;
    uint32_t* bmh = aml + 2304;    // 128*36 = 4608
    uint32_t* bml = bmh + 4608;
    int tid = threadIdx.x, lane = tid & 31, wid = tid >> 5;
    int q = lane >> 2, r = lane & 3;
    size_t rbase = (size_t)blockIdx.x * 64;
    int wm  = (wid & 1) << 5;
    int wnn = (wid >> 1) << 5;

    const uint4* a4h = (const uint4*)(ah + rbase*32);
    const uint4* a4l = (const uint4*)(al + rbase*32);
    for (int i = tid; i < 512; i += 256){
        int row = i >> 3, c4 = (i & 7) << 2;
        *(uint4*)&amh[row*36 + c4] = a4h[i];
        *(uint4*)&aml[row*36 + c4] = a4l[i];
    }
    const uint4* b4h = (const uint4*)bh;
    const uint4* b4l = (const uint4*)bl;
    for (int i = tid; i < 1024; i += 256){
        int n = i >> 3, c4 = (i & 7) << 2;
        *(uint4*)&bmh[n*36 + c4] = b4h[i];
        *(uint4*)&bml[n*36 + c4] = b4l[i];
    }
    __syncthreads();

    int arow0 = wm + (lane & 7) + ((lane >> 3) & 1)*8;
    uint32_t aoff = (uint32_t)(arow0*36 + ((lane >> 4) & 1)*4) * 4;
    uint32_t AH = sptr(amh) + aoff, AL = sptr(aml) + aoff;
    int brow0 = wnn + ((lane >> 4) & 1)*8 + (lane & 7);
    uint32_t boff = (uint32_t)(brow0*36 + ((lane >> 3) & 1)*4) * 4;
    uint32_t BH = sptr(bmh) + boff, BL = sptr(bml) + boff;

    float acc[2][4][4];
    #pragma unroll
    for (int a=0;a<2;a++)
        #pragma unroll
        for (int b=0;b<4;b++)
            #pragma unroll
            for (int c=0;c<4;c++) acc[a][b][c] = 0.f;

    #pragma unroll
    for (int kk = 0; kk < 4; kk++){
        uint32_t Ah[2][4], Al[2][4];
        ldsm4(Ah[0], AH + kk*32);
        ldsm4(Ah[1], AH + 16*36*4 + kk*32);
        ldsm4(Al[0], AL + kk*32);
        ldsm4(Al[1], AL + 16*36*4 + kk*32);
        #pragma unroll
        for (int ntp = 0; ntp < 2; ntp++){
            uint32_t Bh4[4], Bl4[4];
            ldsm4(Bh4, BH + ntp*16*36*4 + kk*32);
            ldsm4(Bl4, BL + ntp*16*36*4 + kk*32);
            #pragma unroll
            for (int mt = 0; mt < 2; mt++){
                mma16(acc[mt][2*ntp],   Ah[mt], &Bh4[0]);
                mma16(acc[mt][2*ntp],   Ah[mt], &Bl4[0]);
                mma16(acc[mt][2*ntp],   Al[mt], &Bh4[0]);
                mma16(acc[mt][2*ntp+1], Ah[mt], &Bh4[2]);
                mma16(acc[mt][2*ntp+1], Ah[mt], &Bl4[2]);
                mma16(acc[mt][2*ntp+1], Al[mt], &Bh4[2]);
            }
        }
    }

    bool left = (wnn < 64);
    float* op = left ? ol : orr;
    int n0 = left ? wnn : (wnn - 64);
    #pragma unroll
    for (int mt = 0; mt < 2; mt++)
        #pragma unroll
        for (int rr = 0; rr < 2; rr++){
            size_t row = rbase + wm + mt*16 + rr*8 + q;
            #pragma unroll
            for (int nt = 0; nt < 4; nt++){
                int oc = n0 + (nt<<3) + (r<<1);
                float2 v = make_float2(acc[mt][nt][rr*2], acc[mt][nt][rr*2+1]);
                *(float2*)(op + row*64 + oc) = v;
            }
        }
}

// ---------------- GATv2 edge aggregation (unchanged) ----------------
__global__ void gat_agg_k(const float* __restrict__ xl, const float* __restrict__ xr,
                          const int* __restrict__ rp, const int* __restrict__ cs,
                          const float* __restrict__ att, const float* __restrict__ bias,
                          uint32_t* __restrict__ oh, uint32_t* __restrict__ olp){
    int gw   = (blockIdx.x*blockDim.x + threadIdx.x) >> 5;
    int lane = threadIdx.x & 31;
    if (gw >= NN) return;
    float2 xi = __ldg(&((const float2*)xr)[gw*32 + lane]);
    float2 av = __ldg(&((const float2*)att)[lane]);
    float den = 0.f, ac0 = 0.f, ac1 = 0.f;
    int k0 = __ldg(&rp[gw]), k1 = __ldg(&rp[gw+1]);
    #pragma unroll 4
    for (int k = k0; k < k1; k++){
        int s = __ldg(&cs[k]);
        float2 xj = __ldg(&((const float2*)xl)[s*32 + lane]);
        float t0 = xi.x + xj.x; t0 = fmaxf(t0, 0.2f*t0);
        float t1 = xi.y + xj.y; t1 = fmaxf(t1, 0.2f*t1);
        float p = av.x*t0 + av.y*t1;
        p += __shfl_xor_sync(0xffffffffu, p, 1);
        p += __shfl_xor_sync(0xffffffffu, p, 2);
        p += __shfl_xor_sync(0xffffffffu, p, 4);
        float w = __expf(p);
        den += w;
        ac0 += w*xj.x;
        ac1 += w*xj.y;
    }
    float2 bv = __ldg(&((const float2*)bias)[lane]);
    float inv = 1.f/(den + 1e-16f);
    float o0 = ac0*inv + bv.x;
    float o1 = ac1*inv + bv.y;
    o0 = (o0 > 0.f) ? o0 : (__expf(o0) - 1.f);   // ELU
    o1 = (o1 > 0.f) ? o1 : (__expf(o1) - 1.f);
    uint32_t hw, lw; hl2(o0, o1, hw, lw);
    oh [gw*32 + lane] = hw;
    olp[gw*32 + lane] = lw;
}

// ---------------- combine via ldmatrix ----------------
__global__ __launch_bounds__(256, 4)
void combine_mma_k(const uint32_t* __restrict__ b0h, const uint32_t* __restrict__ b0l,
                   const uint32_t* __restrict__ b1h, const uint32_t* __restrict__ b1l,
                   const uint32_t* __restrict__ b2h, const uint32_t* __restrict__ b2l,
                   const uint32_t* __restrict__ cwh, const uint32_t* __restrict__ cwl,
                   const float* __restrict__ bias,
                   float* __restrict__ xio,
                   uint32_t* __restrict__ oph, uint32_t* __restrict__ opl){
    extern __shared__ uint32_t sm[];
    uint32_t* amh = sm;            // 128*36 = 4608
    uint32_t* aml = amh + 4608;
    uint32_t* bmh = aml + 4608;    // 64*36 = 2304
    uint32_t* bml = bmh + 2304;
    int tid = threadIdx.x, lane = tid & 31, wid = tid >> 5;
    int q = lane >> 2, r = lane & 3;
    size_t rbase = (size_t)blockIdx.x * 128;
    int wm = (wid & 3) << 5;
    int wn = (wid >> 2) << 5;

    int arow0 = wm + (lane & 7) + ((lane >> 3) & 1)*8;
    uint32_t aoff = (uint32_t)(arow0*36 + ((lane >> 4) & 1)*4) * 4;
    uint32_t AH = sptr(amh) + aoff, AL = sptr(aml) + aoff;
    int brow0 = wn + ((lane >> 4) & 1)*8 + (lane & 7);
    uint32_t boff = (uint32_t)(brow0*36 + ((lane >> 3) & 1)*4) * 4;
    uint32_t BH = sptr(bmh) + boff, BL = sptr(bml) + boff;

    float acc[2][4][4];
    #pragma unroll
    for (int a=0;a<2;a++)
        #pragma unroll
        for (int b=0;b<4;b++)
            #pragma unroll
            for (int c=0;c<4;c++) acc[a][b][c] = 0.f;

    const uint4* w4h = (const uint4*)cwh;
    const uint4* w4l = (const uint4*)cwl;

    #pragma unroll 1
    for (int cg = 0; cg < 3; cg++){
        const uint32_t* bsh = (cg==0) ? b0h : (cg==1) ? b1h : b2h;
        const uint32_t* bsl = (cg==0) ? b0l : (cg==1) ? b1l : b2l;
        const uint4* s4h = (const uint4*)(bsh + rbase*32);
        const uint4* s4l = (const uint4*)(bsl + rbase*32);
        for (int i = tid; i < 1024; i += 256){
            int row = i >> 3, c4 = (i & 7) << 2;
            *(uint4*)&amh[row*36 + c4] = s4h[i];
            *(uint4*)&aml[row*36 + c4] = s4l[i];
        }
        for (int i = tid; i < 512; i += 256){
            int o = i >> 3, c = i & 7;
            *(uint4*)&bmh[o*36 + (c<<2)] = w4h[o*24 + cg*8 + c];
            *(uint4*)&bml[o*36 + (c<<2)] = w4l[o*24 + cg*8 + c];
        }
        __syncthreads();

        #pragma unroll
        for (int kk = 0; kk < 4; kk++){
            uint32_t Ah[2][4], Al[2][4];
            ldsm4(Ah[0], AH + kk*32);
            ldsm4(Ah[1], AH + 16*36*4 + kk*32);
            ldsm4(Al[0], AL + kk*32);
            ldsm4(Al[1], AL + 16*36*4 + kk*32);
            #pragma unroll
            for (int ntp = 0; ntp < 2; ntp++){
                uint32_t Bh4[4], Bl4[4];
                ldsm4(Bh4, BH + ntp*16*36*4 + kk*32);
                ldsm4(Bl4, BL + ntp*16*36*4 + kk*32);
                #pragma unroll
                for (int mt = 0; mt < 2; mt++){
                    mma16(acc[mt][2*ntp],   Ah[mt], &Bh4[0]);
                    mma16(acc[mt][2*ntp],   Ah[mt], &Bl4[0]);
                    mma16(acc[mt][2*ntp],   Al[mt], &Bh4[0]);
                    mma16(acc[mt][2*ntp+1], Ah[mt], &Bh4[2]);
                    mma16(acc[mt][2*ntp+1], Ah[mt], &Bl4[2]);
                    mma16(acc[mt][2*ntp+1], Al[mt], &Bh4[2]);
                }
            }
        }
        __syncthreads();
    }

    #pragma unroll
    for (int mt = 0; mt < 2; mt++)
        #pragma unroll
        for (int rr = 0; rr < 2; rr++){
            size_t row = rbase + wm + mt*16 + rr*8 + q;
            #pragma unroll
            for (int nt = 0; nt < 4; nt++){
                int oc = wn + (nt<<3) + (r<<1);
                float2 res = *(float2*)(xio + row*64 + oc);
                float v0 = acc[mt][nt][rr*2]   + bias[oc]   + res.x;
                float v1 = acc[mt][nt][rr*2+1] + bias[oc+1] + res.y;
                *(float2*)(xio + row*64 + oc) = make_float2(v0, v1);
                uint32_t hw, lw; hl2(v0, v1, hw, lw);
                oph[row*32 + (oc>>1)] = hw;
                opl[row*32 + (oc>>1)] = lw;
            }
        }
}

// ---------------- 3x3 conv: R11 version (512 blocks x 128 px, plane input) -----
// mode 0: planes(PReLU(conv+bias)) only;  mode 1: fp32 out += conv+bias, + planes
__global__ void conv3_mma_k(const uint32_t* __restrict__ inh,
                            const uint32_t* __restrict__ inl,
                            const uint32_t* __restrict__ wbh,
                            const uint32_t* __restrict__ wbl,
                            const float* __restrict__ bias,
                            const float* __restrict__ aptr,
                            float* __restrict__ out, int mode,
                            uint32_t* __restrict__ ph, uint32_t* __restrict__ pl){
    extern __shared__ uint32_t sm[];
    uint32_t* amh = sm;            // 3*132*12 = 4752
    uint32_t* aml = amh + 4752;
    uint32_t* bmh = aml + 4752;    // 64*76 = 4864
    uint32_t* bml = bmh + 4864;
    int tid = threadIdx.x, lane = tid & 31, wid = tid >> 5;
    int q = lane >> 2, r = lane & 3;
    int h  = blockIdx.x >> 1;
    int w0 = (blockIdx.x & 1) << 7;
    int wpx = (wid & 3) << 5;
    int wn  = (wid >> 2) << 5;

    int pxo  = (lane & 7) + ((lane >> 3) & 1)*8;
    uint32_t akp = ((lane >> 4) & 1)*4;
    uint32_t AHb = sptr(amh) + akp*4;
    uint32_t ALb = sptr(aml) + akp*4;
    int brow0 = wn + ((lane >> 4) & 1)*8 + (lane & 7);
    uint32_t boff = (uint32_t)(brow0*76 + ((lane >> 3) & 1)*4) * 4;
    uint32_t BH = sptr(bmh) + boff, BL = sptr(bml) + boff;

    float acc[2][4][4];
    #pragma unroll
    for (int a=0;a<2;a++)
        #pragma unroll
        for (int b=0;b<4;b++)
            #pragma unroll
            for (int c=0;c<4;c++) acc[a][b][c] = 0.f;

    for (int chunk = 0; chunk < 4; chunk++){
        const uint4* wh4 = (const uint4*)(wbh + chunk*4608);
        const uint4* wl4 = (const uint4*)(wbl + chunk*4608);
        for (int i = tid; i < 1152; i += 256){
            int oc = i / 18, w4 = i - oc*18;
            *(uint4*)&bmh[oc*76 + (w4<<2)] = wh4[i];
            *(uint4*)&bml[oc*76 + (w4<<2)] = wl4[i];
        }
        for (int i = tid; i < 1560; i += 256){
            int pos = i >> 2, sel = i & 3;
            int kh = pos / 130, col = pos - kh*130;
            int gh = h - 1 + kh, gw = w0 - 1 + col;
            uint4 v = make_uint4(0u,0u,0u,0u);
            const uint32_t* srcp = (sel >> 1) ? inl : inh;
            if ((unsigned)gh < 256u && (unsigned)gw < 256u)
                v = *(const uint4*)(srcp + ((size_t)((gh<<8)+gw))*32 + (chunk<<3) + ((sel&1)<<2));
            uint32_t* dstp = (sel >> 1) ? aml : amh;
            *(uint4*)&dstp[(kh*132 + col)*12 + ((sel&1)<<2)] = v;
        }
        __syncthreads();

        #pragma unroll
        for (int t = 0; t < 9; t++){
            int kh = t/3, kw = t - (t/3)*3;
            uint32_t Ah[2][4], Al[2][4];
            #pragma unroll
            for (int mt = 0; mt < 2; mt++){
                uint32_t ao = (uint32_t)((kh*132 + wpx + kw + pxo + mt*16)*12) * 4;
                ldsm4(Ah[mt], AHb + ao);
                ldsm4(Al[mt], ALb + ao);
            }
            #pragma unroll
            for (int ntp = 0; ntp < 2; ntp++){
                uint32_t Bh4[4], Bl4[4];
                ldsm4(Bh4, BH + (uint32_t)(ntp*16*76 + t*8)*4);
                ldsm4(Bl4, BL + (uint32_t)(ntp*16*76 + t*8)*4);
                #pragma unroll
                for (int mt = 0; mt < 2; mt++){
                    mma16(acc[mt][2*ntp],   Ah[mt], &Bh4[0]);
                    mma16(acc[mt][2*ntp],   Ah[mt], &Bl4[0]);
                    mma16(acc[mt][2*ntp],   Al[mt], &Bh4[0]);
                    mma16(acc[mt][2*ntp+1], Ah[mt], &Bh4[2]);
                    mma16(acc[mt][2*ntp+1], Ah[mt], &Bl4[2]);
                    mma16(acc[mt][2*ntp+1], Al[mt], &Bh4[2]);
                }
            }
        }
        __syncthreads();
    }

    float a = aptr[0];
    #pragma unroll
    for (int mt = 0; mt < 2; mt++)
        #pragma unroll
        for (int rr = 0; rr < 2; rr++){
            int px = wpx + mt*16 + rr*8 + q;
            size_t node = ((size_t)h << 8) + w0 + px;
            #pragma unroll
            for (int nt = 0; nt < 4; nt++){
                int oc = wn + (nt<<3) + (r<<1);
                float v0 = acc[mt][nt][rr*2]   + bias[oc];
                float v1 = acc[mt][nt][rr*2+1] + bias[oc+1];
                if (mode == 0){
                    v0 = (v0 >= 0.f) ? v0 : a*v0;
                    v1 = (v1 >= 0.f) ? v1 : a*v1;
                } else {
                    float* op = out + node*64 + oc;
                    float2 cur = *(float2*)op;
                    v0 += cur.x; v1 += cur.y;
                    *(float2*)op = make_float2(v0, v1);
                }
                uint32_t hw, lw; hl2(v0, v1, hw, lw);
                ph[node*32 + (oc>>1)] = hw;
                pl[node*32 + (oc>>1)] = lw;
            }
        }
}

// ---------------- host orchestration ----------------
extern "C" void kernel_launch(void* const* d_in, const int* in_sizes, int n_in,
                              void* d_out, int out_size){
    const float* x    = (const float*)d_in[0];
    const int*   ei   = (const int*)  d_in[1];
    const float* gWl  = (const float*)d_in[2];
    const float* gWr  = (const float*)d_in[3];
    const float* gatt = (const float*)d_in[4];
    const float* gb   = (const float*)d_in[5];
    const float* ccw  = (const float*)d_in[6];
    const float* ccb  = (const float*)d_in[7];
    const float* rbw  = (const float*)d_in[8];
    const float* rbb  = (const float*)d_in[9];
    const float* rba  = (const float*)d_in[10];
    float* outp = (float*)d_out;

    float *xn,*xl0,*xr0,*xl1,*xr1,*xl2,*xr2;
    uint32_t *xnh,*xnl,*tph,*tpl,*bph,*bpl,*gwh,*gwl,*cwh,*cwl,*wbh,*wbl;
    int *rp,*cnt,*csrc;
    cudaGetSymbolAddress((void**)&xn,  g_xn);
    cudaGetSymbolAddress((void**)&xl0, g_xl0);
    cudaGetSymbolAddress((void**)&xr0, g_xr0);
    cudaGetSymbolAddress((void**)&xl1, g_xl1);
    cudaGetSymbolAddress((void**)&xr1, g_xr1);
    cudaGetSymbolAddress((void**)&xl2, g_xl2);
    cudaGetSymbolAddress((void**)&xr2, g_xr2);
    cudaGetSymbolAddress((void**)&xnh, g_xnh);
    cudaGetSymbolAddress((void**)&xnl, g_xnl);
    cudaGetSymbolAddress((void**)&tph, g_tph);
    cudaGetSymbolAddress((void**)&tpl, g_tpl);
    cudaGetSymbolAddress((void**)&bph, g_bph);
    cudaGetSymbolAddress((void**)&bpl, g_bpl);
    cudaGetSymbolAddress((void**)&gwh, g_gwh);
    cudaGetSymbolAddress((void**)&gwl, g_gwl);
    cudaGetSymbolAddress((void**)&cwh, g_cwh);
    cudaGetSymbolAddress((void**)&cwl, g_cwl);
    cudaGetSymbolAddress((void**)&wbh, g_wbh);
    cudaGetSymbolAddress((void**)&wbl, g_wbl);
    cudaGetSymbolAddress((void**)&rp,  g_rp);
    cudaGetSymbolAddress((void**)&cnt, g_cnt);
    cudaGetSymbolAddress((void**)&csrc,g_csrc);

    const int smem_gemm = 13824*4;   // 55296 B
    const int smem_comb = 13824*4;   // 55296 B
    const int smem_conv = 19232*4;   // 76928 B
    cudaFuncSetAttribute(gemm_dual_mma_k, cudaFuncAttributeMaxDynamicSharedMemorySize, smem_gemm);
    cudaFuncSetAttribute(combine_mma_k,   cudaFuncAttributeMaxDynamicSharedMemorySize, smem_comb);
    cudaFuncSetAttribute(conv3_mma_k,     cudaFuncAttributeMaxDynamicSharedMemorySize, smem_conv);

    bool async_ok = g_hx.ok;
    cudaStream_t st1 = async_ok ? g_hx.s1 : (cudaStream_t)0;
    cudaStream_t st2 = async_ok ? g_hx.s2 : (cudaStream_t)0;

    // ---- head: CSR + weight transforms forked onto side streams ----
    if (async_ok){
        cudaEventRecord(g_hx.e0, 0);
        cudaStreamWaitEvent(st1, g_hx.e0, 0);
        cudaStreamWaitEvent(st2, g_hx.e0, 0);
    }
    // side stream 1: CSR build (depends only on ei)
    zero_int_k<<<NN/256, 256, 0, st1>>>(cnt, NN);
    hist_k<<<NEDGE/256, 256, 0, st1>>>(ei + NEDGE, cnt);
    scan_k<<<1, 1024, 0, st1>>>(cnt, rp);
    fill_k<<<NEDGE/256, 256, 0, st1>>>(ei, ei + NEDGE, rp, cnt, csrc);
    if (async_ok) cudaEventRecord(g_hx.e1, st1);
    // side stream 2: conv + combine weight transforms
    wtrans_bf16_k<<<(16*4*64*72)/256, 256, 0, st2>>>(rbw, wbh, wbl);
    wtrans_cc_k<<<(3*64*96)/256, 256, 0, st2>>>(ccw, cwh, cwl);
    if (async_ok) cudaEventRecord(g_hx.e2, st2);
    // main stream: input staging + gat weights + first gemm
    transpose_k<<<dim3(2048,2), dim3(32,8)>>>(x, xn, 64, 65536);
    cvt_planes_k<<<(NN*32)/256, 256>>>(xn, xnh, xnl);
    wtrans_gat_k<<<(27*128*32)/256, 256>>>(gWl, gWr, gwh, gwl);
    gemm_dual_mma_k<<<1024, 256, smem_gemm>>>(xnh, xnl, gwh, gwl, xl0, xr0);
    if (async_ok){
        cudaStreamWaitEvent((cudaStream_t)0, g_hx.e1, 0);   // CSR ready
        cudaStreamWaitEvent((cudaStream_t)0, g_hx.e2, 0);   // weights ready
    }

    float* xlv[3] = {xl0, xl1, xl2};
    float* xrv[3] = {xr0, xr1, xr2};

    for (int st = 0; st < 3; st++){
        if (async_ok){
            cudaEventRecord(g_hx.ef, 0);
            cudaStreamWaitEvent(st1, g_hx.ef, 0);
            cudaStreamWaitEvent(st2, g_hx.ef, 0);
        }
        for (int mb = 0; mb < 3; mb++){
            cudaStream_t ss = (mb==0) ? (cudaStream_t)0 : (mb==1 ? st1 : st2);
            float* cxl = xlv[mb];
            float* cxr = xrv[mb];
            const uint32_t* curh = xnh;
            const uint32_t* curl = xnl;
            for (int l = 0; l < 3; l++){
                int wi = (st*3 + mb)*3 + l;
                uint32_t* dh = (l==0) ? (tph + (size_t)mb*NN*32) : (bph + (size_t)mb*NN*32);
                uint32_t* dl = (l==0) ? (tpl + (size_t)mb*NN*32) : (bpl + (size_t)mb*NN*32);
                if (!(st==0 && mb==0 && l==0))   // that gemm was pre-launched
                    gemm_dual_mma_k<<<1024, 256, smem_gemm, ss>>>(curh, curl,
                        gwh + (size_t)wi*4096, gwl + (size_t)wi*4096, cxl, cxr);
                gat_agg_k<<<(NN*32)/256, 256, 0, ss>>>(cxl, cxr, rp, csrc,
                        gatt + (size_t)wi*64, gb + (size_t)wi*64, dh, dl);
                curh = dh; curl = dl;
            }
        }
        if (async_ok){
            cudaEventRecord(g_hx.e1, st1);
            cudaEventRecord(g_hx.e2, st2);
            cudaStreamWaitEvent((cudaStream_t)0, g_hx.e1, 0);
            cudaStreamWaitEvent((cudaStream_t)0, g_hx.e2, 0);
        }
        combine_mma_k<<<512, 256, smem_comb>>>(
            bph, bpl,
            bph + (size_t)NN*32, bpl + (size_t)NN*32,
            bph + (size_t)2*NN*32, bpl + (size_t)2*NN*32,
            cwh + (size_t)st*6144, cwl + (size_t)st*6144,
            ccb + (size_t)st*64, xn, xnh, xnl);
        if (st < 2){
            for (int bl = 0; bl < 4; bl++){
                int cidx = st*8 + bl*2;
                conv3_mma_k<<<512, 256, smem_conv>>>(xnh, xnl,
                                                     wbh + (size_t)cidx*18432,
                                                     wbl + (size_t)cidx*18432,
                                                     rbb + (size_t)cidx*64,
                                                     rba + st*4 + bl, xl0, 0,
                                                     tph, tpl);
                conv3_mma_k<<<512, 256, smem_conv>>>(tph, tpl,
                                                     wbh + (size_t)(cidx+1)*18432,
                                                     wbl + (size_t)(cidx+1)*18432,
                                                     rbb + (size_t)(cidx+1)*64,
                                                     rba + st*4 + bl, xn, 1,
                                                     xnh, xnl);
            }
        }
    }
    transpose_k<<<dim3(2,2048), dim3(32,8)>>>(xn, outp, 65536, 64);
}